// round 12
// baseline (speedup 1.0000x reference)
#include <cuda_runtime.h>
#include <cuda_bf16.h>
#include <cstdint>

#define DIMS        128
#define GAMMA       12.0f
#define MAX_NODES   100000
#define MAX_EDGES   600000
#define SCAN_BLK    1024
#define SCAN_NB     ((MAX_NODES + SCAN_BLK - 1) / SCAN_BLK)   // 98

// ---- device scratch (allocation-free requirement) ------------------------
__device__ int  g_counts[MAX_NODES];       // histogram
__device__ int  g_cursor[MAX_NODES];       // scatter cursors
__device__ int  g_offsets[MAX_NODES + 1];  // CSR offsets
__device__ int2 g_edge[MAX_EDGES];         // (edge_id, src_id) grouped by dst
__device__ int  g_blocksums[SCAN_NB];

// L2 evict-last policy (pin the node table).
__device__ __forceinline__ uint64_t make_evict_last_policy() {
    uint64_t pol;
    asm("createpolicy.fractional.L2::evict_last.b64 %0, 1.0;" : "=l"(pol));
    return pol;
}
__device__ __forceinline__ float4 ldg_pin_l2(const float4* p, uint64_t pol) {
    float4 v;
    asm volatile("ld.global.nc.L2::cache_hint.v4.f32 {%0,%1,%2,%3}, [%4], %5;"
                 : "=f"(v.x), "=f"(v.y), "=f"(v.z), "=f"(v.w)
                 : "l"(p), "l"(pol));
    return v;
}
__device__ __forceinline__ float4 ldg_stream(const float4* p) {
    float4 v;
    asm volatile("ld.global.cs.v4.f32 {%0,%1,%2,%3}, [%4];"
                 : "=f"(v.x), "=f"(v.y), "=f"(v.z), "=f"(v.w)
                 : "l"(p));
    return v;
}
__device__ __forceinline__ void stg_stream(float4* p, float4 v) {
    asm volatile("st.global.cs.v4.f32 [%0], {%1,%2,%3,%4};"
                 :: "l"(p), "f"(v.x), "f"(v.y), "f"(v.z), "f"(v.w)
                 : "memory");
}

// ---- phase 1: build dst-CSR ---------------------------------------------
__global__ void k_zero_counts(int N) {
    int i = blockIdx.x * blockDim.x + threadIdx.x;
    if (i < N) g_counts[i] = 0;
}

__global__ void k_hist(const int* __restrict__ dst, int E) {
    int e = blockIdx.x * blockDim.x + threadIdx.x;
    if (e < E) {
        int* p = &g_counts[dst[e]];
        asm volatile("red.global.add.s32 [%0], 1;" :: "l"(p) : "memory");
    }
}

// per-block inclusive scan of counts; exclusive result -> offsets,
// block totals -> blocksums
__global__ void k_scan1(int N) {
    __shared__ int sm[SCAN_BLK];
    int i = blockIdx.x * SCAN_BLK + threadIdx.x;
    int v = (i < N) ? g_counts[i] : 0;
    sm[threadIdx.x] = v;
    __syncthreads();
    for (int off = 1; off < SCAN_BLK; off <<= 1) {
        int t = (threadIdx.x >= off) ? sm[threadIdx.x - off] : 0;
        __syncthreads();
        sm[threadIdx.x] += t;
        __syncthreads();
    }
    if (i < N) g_offsets[i] = sm[threadIdx.x] - v;   // exclusive
    if (threadIdx.x == SCAN_BLK - 1) g_blocksums[blockIdx.x] = sm[threadIdx.x];
}

// scan3 with the blocksum prefix computed inline (98 values -> warp reduce
// + shared atomic). Eliminates the separate k_scan2 launch.
__global__ void k_scan3(int N, int E) {
    __shared__ int s_base;
    if (threadIdx.x == 0) s_base = 0;
    __syncthreads();

    int partial = 0;
    for (int j = threadIdx.x; j < blockIdx.x; j += blockDim.x)
        partial += g_blocksums[j];
    #pragma unroll
    for (int off = 16; off > 0; off >>= 1)
        partial += __shfl_xor_sync(0xffffffffu, partial, off);
    if ((threadIdx.x & 31) == 0 && partial != 0)
        atomicAdd(&s_base, partial);
    __syncthreads();

    const int base = s_base;
    int i = blockIdx.x * SCAN_BLK + threadIdx.x;
    if (i < N) {
        int o = g_offsets[i] + base;
        g_offsets[i] = o;
        g_cursor[i]  = o;
    }
    if (blockIdx.x == 0 && threadIdx.x == 0) g_offsets[N] = E;
}

// scatter packed (edge_id, src_id) so the main loop has ONE index load
// per edge instead of a perm->src dependent chain.
__global__ void k_scatter(const int* __restrict__ dst,
                          const int* __restrict__ src, int E) {
    int e = blockIdx.x * blockDim.x + threadIdx.x;
    if (e < E) {
        int pos = atomicAdd(&g_cursor[dst[e]], 1);
        g_edge[pos] = make_int2(e, src[e]);
    }
}

// ---- phase 2: one warp per dst node, register accumulation, no atomics ---
__device__ __forceinline__ void edge_body(const float* __restrict__ node_emb,
                                          const float* __restrict__ edge_emb,
                                          int2 ed, int lane, uint64_t pol,
                                          const float4& t, float4& acc) {
    const float4 h = ldg_pin_l2(
        reinterpret_cast<const float4*>(node_emb + (size_t)ed.y * DIMS) + lane, pol);
    const float4 r = ldg_stream(
        reinterpret_cast<const float4*>(edge_emb + (size_t)ed.x * DIMS) + lane);
    float4 tr;
    tr.x = h.x + r.x; tr.y = h.y + r.y; tr.z = h.z + r.z; tr.w = h.w + r.w;
    float dx = tr.x - t.x, dy = tr.y - t.y, dz = tr.z - t.z, dw = tr.w - t.w;
    float ss = dx * dx + dy * dy + dz * dz + dw * dw;
    #pragma unroll
    for (int off = 16; off > 0; off >>= 1)
        ss += __shfl_xor_sync(0xffffffffu, ss, off);
    const float sc = 1.0f / (1.0f + __expf(sqrtf(ss) - GAMMA));
    acc.x += sc * tr.x; acc.y += sc * tr.y;
    acc.z += sc * tr.z; acc.w += sc * tr.w;
}

__global__ __launch_bounds__(256)
void transe_node_kernel(const float* __restrict__ node_emb,
                        const float* __restrict__ edge_emb,
                        float*       __restrict__ out,
                        int N) {
    const int warp = (blockIdx.x * blockDim.x + threadIdx.x) >> 5;
    const int lane = threadIdx.x & 31;
    if (warp >= N) return;

    const uint64_t pol = make_evict_last_policy();

    const int begin = __ldg(&g_offsets[warp]);
    const int end   = __ldg(&g_offsets[warp + 1]);

    float4 acc = make_float4(0.f, 0.f, 0.f, 0.f);

    if (begin < end) {
        // tail row loaded ONCE per node
        const float4 t = ldg_pin_l2(
            reinterpret_cast<const float4*>(node_emb + (size_t)warp * DIMS) + lane, pol);

        int e = begin;
        // 4-edge batches: 8 vector loads in flight, 4 interleaved shfl
        // chains, 4 interleaved sigmoids.
        for (; e + 3 < end; e += 4) {
            const int2 ed0 = __ldg(g_edge + e);
            const int2 ed1 = __ldg(g_edge + e + 1);
            const int2 ed2 = __ldg(g_edge + e + 2);
            const int2 ed3 = __ldg(g_edge + e + 3);

            float4 h[4], r[4];
            h[0] = ldg_pin_l2(reinterpret_cast<const float4*>(node_emb + (size_t)ed0.y * DIMS) + lane, pol);
            h[1] = ldg_pin_l2(reinterpret_cast<const float4*>(node_emb + (size_t)ed1.y * DIMS) + lane, pol);
            h[2] = ldg_pin_l2(reinterpret_cast<const float4*>(node_emb + (size_t)ed2.y * DIMS) + lane, pol);
            h[3] = ldg_pin_l2(reinterpret_cast<const float4*>(node_emb + (size_t)ed3.y * DIMS) + lane, pol);
            r[0] = ldg_stream(reinterpret_cast<const float4*>(edge_emb + (size_t)ed0.x * DIMS) + lane);
            r[1] = ldg_stream(reinterpret_cast<const float4*>(edge_emb + (size_t)ed1.x * DIMS) + lane);
            r[2] = ldg_stream(reinterpret_cast<const float4*>(edge_emb + (size_t)ed2.x * DIMS) + lane);
            r[3] = ldg_stream(reinterpret_cast<const float4*>(edge_emb + (size_t)ed3.x * DIMS) + lane);

            float4 tr[4];
            float ss[4];
            #pragma unroll
            for (int i = 0; i < 4; i++) {
                tr[i].x = h[i].x + r[i].x;
                tr[i].y = h[i].y + r[i].y;
                tr[i].z = h[i].z + r[i].z;
                tr[i].w = h[i].w + r[i].w;
                const float dx = tr[i].x - t.x;
                const float dy = tr[i].y - t.y;
                const float dz = tr[i].z - t.z;
                const float dw = tr[i].w - t.w;
                ss[i] = dx * dx + dy * dy + dz * dz + dw * dw;
            }

            #pragma unroll
            for (int off = 16; off > 0; off >>= 1) {
                #pragma unroll
                for (int i = 0; i < 4; i++)
                    ss[i] += __shfl_xor_sync(0xffffffffu, ss[i], off);
            }

            float sc[4];
            #pragma unroll
            for (int i = 0; i < 4; i++)
                sc[i] = 1.0f / (1.0f + __expf(sqrtf(ss[i]) - GAMMA));

            #pragma unroll
            for (int i = 0; i < 4; i++) {
                acc.x += sc[i] * tr[i].x;
                acc.y += sc[i] * tr[i].y;
                acc.z += sc[i] * tr[i].z;
                acc.w += sc[i] * tr[i].w;
            }
        }
        for (; e < end; e++) {
            const int2 ed = __ldg(g_edge + e);
            edge_body(node_emb, edge_emb, ed, lane, pol, t, acc);
        }
    }

    // each output row written exactly once -> streaming store, no zero-init
    stg_stream(reinterpret_cast<float4*>(out + (size_t)warp * DIMS) + lane, acc);
}

// -------------------------------------------------------------------------
// Harness entry. Inputs (metadata order):
//   d_in[0] node_emb  float32 [N,128]
//   d_in[1] edge_emb  float32 [E,128]
//   d_in[2] src       int32   [E]
//   d_in[3] dst       int32   [E]
// d_out: float32 [N,128]
// -------------------------------------------------------------------------
extern "C" void kernel_launch(void* const* d_in, const int* in_sizes, int n_in,
                              void* d_out, int out_size) {
    const float* node_emb = (const float*)d_in[0];
    const float* edge_emb = (const float*)d_in[1];
    const int*   src      = (const int*)d_in[2];
    const int*   dst      = (const int*)d_in[3];
    float*       out      = (float*)d_out;

    const int E = in_sizes[2];
    const int N = out_size / DIMS;

    const int TB = 256;
    const int nbN = (N + TB - 1) / TB;
    const int nbE = (E + TB - 1) / TB;

    k_zero_counts<<<nbN, TB>>>(N);
    k_hist<<<nbE, TB>>>(dst, E);
    k_scan1<<<(N + SCAN_BLK - 1) / SCAN_BLK, SCAN_BLK>>>(N);
    k_scan3<<<(N + SCAN_BLK - 1) / SCAN_BLK, SCAN_BLK>>>(N, E);
    k_scatter<<<nbE, TB>>>(dst, src, E);

    // one warp per node
    const int warpsPerBlock = TB / 32;
    const int nbMain = (N + warpsPerBlock - 1) / warpsPerBlock;
    transe_node_kernel<<<nbMain, TB>>>(node_emb, edge_emb, out, N);
}

// round 13
// speedup vs baseline: 1.1603x; 1.1603x over previous
#include <cuda_runtime.h>
#include <cuda_bf16.h>
#include <cstdint>

#define DIMS        128
#define GAMMA       12.0f
#define MAX_NODES   100000
#define MAX_EDGES   600000
#define SETUP_BLK   1024
#define SETUP_NB    ((MAX_NODES + SETUP_BLK - 1) / SETUP_BLK)   // 98 (< 148 SMs)

// ---- device scratch (allocation-free requirement) ------------------------
__device__ int      g_counts[MAX_NODES];       // histogram
__device__ int      g_cursor[MAX_NODES];       // scatter cursors
__device__ int      g_offsets[MAX_NODES + 1];  // CSR offsets
__device__ int2     g_edge[MAX_EDGES];         // (edge_id, src_id) grouped by dst
__device__ int      g_blocksums[SETUP_NB];
__device__ unsigned g_bar;                     // grid-barrier counter (reset by main)

// L2 evict-last policy (pin the node table).
__device__ __forceinline__ uint64_t make_evict_last_policy() {
    uint64_t pol;
    asm("createpolicy.fractional.L2::evict_last.b64 %0, 1.0;" : "=l"(pol));
    return pol;
}
__device__ __forceinline__ float4 ldg_pin_l2(const float4* p, uint64_t pol) {
    float4 v;
    asm volatile("ld.global.nc.L2::cache_hint.v4.f32 {%0,%1,%2,%3}, [%4], %5;"
                 : "=f"(v.x), "=f"(v.y), "=f"(v.z), "=f"(v.w)
                 : "l"(p), "l"(pol));
    return v;
}
__device__ __forceinline__ float4 ldg_stream(const float4* p) {
    float4 v;
    asm volatile("ld.global.cs.v4.f32 {%0,%1,%2,%3}, [%4];"
                 : "=f"(v.x), "=f"(v.y), "=f"(v.z), "=f"(v.w)
                 : "l"(p));
    return v;
}
__device__ __forceinline__ void stg_stream(float4* p, float4 v) {
    asm volatile("st.global.cs.v4.f32 [%0], {%1,%2,%3,%4};"
                 :: "l"(p), "f"(v.x), "f"(v.y), "f"(v.z), "f"(v.w)
                 : "memory");
}

// Software grid barrier: valid because all SETUP_NB (=98) blocks are
// co-resident in wave 1 (98 < 148 SMs, 1024 thr/block fits 1 block/SM).
// g_bar monotonically increases; each barrier waits for a higher target.
// g_bar is reset to 0 by the MAIN kernel (safe: setup fully done by then).
__device__ __forceinline__ void grid_barrier(unsigned target) {
    __threadfence();
    __syncthreads();
    if (threadIdx.x == 0) {
        atomicAdd(&g_bar, 1u);
        while (*(volatile unsigned*)&g_bar < target)
            __nanosleep(32);
    }
    __syncthreads();
    __threadfence();
}

// ---- phase 1 (ONE launch): zero -> hist -> scan -> scatter ---------------
__global__ __launch_bounds__(SETUP_BLK, 1)
void k_build_csr(const int* __restrict__ dst,
                 const int* __restrict__ src,
                 int N, int E) {
    __shared__ int sm[SETUP_BLK];
    __shared__ int s_base;

    const int tid    = threadIdx.x;
    const int gtid   = blockIdx.x * SETUP_BLK + tid;
    const int nthr   = gridDim.x * SETUP_BLK;
    unsigned  target = 0;

    // ---- phase 0: zero counts ----
    if (gtid < N) g_counts[gtid] = 0;
    target += gridDim.x;  grid_barrier(target);

    // ---- phase 1: histogram over dst ----
    for (int e = gtid; e < E; e += nthr) {
        int* p = &g_counts[dst[e]];
        asm volatile("red.global.add.s32 [%0], 1;" :: "l"(p) : "memory");
    }
    target += gridDim.x;  grid_barrier(target);

    // ---- phase 2a: block-local inclusive scan of counts chunk ----
    // counts were modified via L2 atomics by other SMs -> read via L2 (.cg)
    int v = (gtid < N) ? __ldcg(&g_counts[gtid]) : 0;
    sm[tid] = v;
    __syncthreads();
    for (int off = 1; off < SETUP_BLK; off <<= 1) {
        int t = (tid >= off) ? sm[tid - off] : 0;
        __syncthreads();
        sm[tid] += t;
        __syncthreads();
    }
    const int excl = sm[tid] - v;   // exclusive within block
    if (tid == SETUP_BLK - 1) g_blocksums[blockIdx.x] = sm[tid];
    target += gridDim.x;  grid_barrier(target);

    // ---- phase 2b: add cross-block base, write offsets + cursors ----
    if (tid == 0) s_base = 0;
    __syncthreads();
    {
        int partial = 0;
        for (int j = tid; j < blockIdx.x; j += SETUP_BLK)
            partial += __ldcg(&g_blocksums[j]);
        #pragma unroll
        for (int off = 16; off > 0; off >>= 1)
            partial += __shfl_xor_sync(0xffffffffu, partial, off);
        if ((tid & 31) == 0 && partial != 0)
            atomicAdd(&s_base, partial);
    }
    __syncthreads();
    if (gtid < N) {
        const int o = excl + s_base;
        g_offsets[gtid] = o;
        g_cursor[gtid]  = o;
    }
    if (gtid == 0) g_offsets[N] = E;
    target += gridDim.x;  grid_barrier(target);

    // ---- phase 3: scatter packed (edge_id, src_id) grouped by dst ----
    for (int e = gtid; e < E; e += nthr) {
        int pos = atomicAdd(&g_cursor[dst[e]], 1);
        g_edge[pos] = make_int2(e, src[e]);
    }
}

// ---- phase 2: one warp per dst node, register accumulation, no atomics ---
__device__ __forceinline__ void edge_body(const float* __restrict__ node_emb,
                                          const float* __restrict__ edge_emb,
                                          int2 ed, int lane, uint64_t pol,
                                          const float4& t, float4& acc) {
    const float4 h = ldg_pin_l2(
        reinterpret_cast<const float4*>(node_emb + (size_t)ed.y * DIMS) + lane, pol);
    const float4 r = ldg_stream(
        reinterpret_cast<const float4*>(edge_emb + (size_t)ed.x * DIMS) + lane);
    float4 tr;
    tr.x = h.x + r.x; tr.y = h.y + r.y; tr.z = h.z + r.z; tr.w = h.w + r.w;
    float dx = tr.x - t.x, dy = tr.y - t.y, dz = tr.z - t.z, dw = tr.w - t.w;
    float ss = dx * dx + dy * dy + dz * dz + dw * dw;
    #pragma unroll
    for (int off = 16; off > 0; off >>= 1)
        ss += __shfl_xor_sync(0xffffffffu, ss, off);
    const float sc = 1.0f / (1.0f + __expf(sqrtf(ss) - GAMMA));
    acc.x += sc * tr.x; acc.y += sc * tr.y;
    acc.z += sc * tr.z; acc.w += sc * tr.w;
}

__global__ __launch_bounds__(256)
void transe_node_kernel(const float* __restrict__ node_emb,
                        const float* __restrict__ edge_emb,
                        float*       __restrict__ out,
                        int N) {
    // reset the grid-barrier counter for the next replay (setup is done)
    if (blockIdx.x == 0 && threadIdx.x == 0) g_bar = 0;

    const int warp = (blockIdx.x * blockDim.x + threadIdx.x) >> 5;
    const int lane = threadIdx.x & 31;
    if (warp >= N) return;

    const uint64_t pol = make_evict_last_policy();

    const int begin = __ldg(&g_offsets[warp]);
    const int end   = __ldg(&g_offsets[warp + 1]);

    float4 acc = make_float4(0.f, 0.f, 0.f, 0.f);

    if (begin < end) {
        // tail row loaded ONCE per node
        const float4 t = ldg_pin_l2(
            reinterpret_cast<const float4*>(node_emb + (size_t)warp * DIMS) + lane, pol);

        int e = begin;
        // two-edge unroll (R9 sweet spot: 4 vector loads in flight,
        // 2 interleaved shfl chains, no register blowup)
        for (; e + 1 < end; e += 2) {
            const int2 ed0 = __ldg(g_edge + e);
            const int2 ed1 = __ldg(g_edge + e + 1);

            const float4 h0 = ldg_pin_l2(
                reinterpret_cast<const float4*>(node_emb + (size_t)ed0.y * DIMS) + lane, pol);
            const float4 r0 = ldg_stream(
                reinterpret_cast<const float4*>(edge_emb + (size_t)ed0.x * DIMS) + lane);
            const float4 h1 = ldg_pin_l2(
                reinterpret_cast<const float4*>(node_emb + (size_t)ed1.y * DIMS) + lane, pol);
            const float4 r1 = ldg_stream(
                reinterpret_cast<const float4*>(edge_emb + (size_t)ed1.x * DIMS) + lane);

            float4 tr0, tr1;
            tr0.x = h0.x + r0.x; tr0.y = h0.y + r0.y;
            tr0.z = h0.z + r0.z; tr0.w = h0.w + r0.w;
            tr1.x = h1.x + r1.x; tr1.y = h1.y + r1.y;
            tr1.z = h1.z + r1.z; tr1.w = h1.w + r1.w;

            float dx, dy, dz, dw;
            dx = tr0.x - t.x; dy = tr0.y - t.y; dz = tr0.z - t.z; dw = tr0.w - t.w;
            float ss0 = dx * dx + dy * dy + dz * dz + dw * dw;
            dx = tr1.x - t.x; dy = tr1.y - t.y; dz = tr1.z - t.z; dw = tr1.w - t.w;
            float ss1 = dx * dx + dy * dy + dz * dz + dw * dw;

            #pragma unroll
            for (int off = 16; off > 0; off >>= 1) {
                ss0 += __shfl_xor_sync(0xffffffffu, ss0, off);
                ss1 += __shfl_xor_sync(0xffffffffu, ss1, off);
            }

            const float sc0 = 1.0f / (1.0f + __expf(sqrtf(ss0) - GAMMA));
            const float sc1 = 1.0f / (1.0f + __expf(sqrtf(ss1) - GAMMA));

            acc.x += sc0 * tr0.x + sc1 * tr1.x;
            acc.y += sc0 * tr0.y + sc1 * tr1.y;
            acc.z += sc0 * tr0.z + sc1 * tr1.z;
            acc.w += sc0 * tr0.w + sc1 * tr1.w;
        }
        if (e < end) {
            const int2 ed = __ldg(g_edge + e);
            edge_body(node_emb, edge_emb, ed, lane, pol, t, acc);
        }
    }

    // each output row written exactly once -> streaming store, no zero-init
    stg_stream(reinterpret_cast<float4*>(out + (size_t)warp * DIMS) + lane, acc);
}

// -------------------------------------------------------------------------
// Harness entry. Inputs (metadata order):
//   d_in[0] node_emb  float32 [N,128]
//   d_in[1] edge_emb  float32 [E,128]
//   d_in[2] src       int32   [E]
//   d_in[3] dst       int32   [E]
// d_out: float32 [N,128]
// -------------------------------------------------------------------------
extern "C" void kernel_launch(void* const* d_in, const int* in_sizes, int n_in,
                              void* d_out, int out_size) {
    const float* node_emb = (const float*)d_in[0];
    const float* edge_emb = (const float*)d_in[1];
    const int*   src      = (const int*)d_in[2];
    const int*   dst      = (const int*)d_in[3];
    float*       out      = (float*)d_out;

    const int E = in_sizes[2];
    const int N = out_size / DIMS;

    // single fused setup launch (co-resident grid, software barriers)
    const int nb = (N + SETUP_BLK - 1) / SETUP_BLK;   // 98 for N=100000
    k_build_csr<<<nb, SETUP_BLK>>>(dst, src, N, E);

    // one warp per node
    const int TB = 256;
    const int warpsPerBlock = TB / 32;
    const int nbMain = (N + warpsPerBlock - 1) / warpsPerBlock;
    transe_node_kernel<<<nbMain, TB>>>(node_emb, edge_emb, out, N);
}